// round 17
// baseline (speedup 1.0000x reference)
#include <cuda_runtime.h>
#include <cstdint>
#include <math.h>

#define NN 50000
#define EE 800000
#define TOT (EE + NN)

// ---------------- device scratch (no allocations allowed) ----------------
__device__ __align__(16) float g_h1[NN * 128];   // layer-1 linear output
__device__ __align__(16) float g_as1[NN * 4];    // per-node attn src terms (4 heads)
__device__ __align__(16) float g_ad1[NN * 4];    // per-node attn dst terms
__device__ __align__(16) float g_h2[NN * 2];     // layer-2 linear output
__device__ float g_as2[NN];
__device__ float g_ad2[NN];
__device__ int g_deg[NN];
__device__ int g_rowptr[NN + 1];
__device__ int g_cursor[NN];
__device__ int g_csr[TOT];
__device__ int g_dstv[TOT];                      // dst node of each CSR slot
__device__ __align__(16) float4 g_p[TOT];        // per-edge softmax weights (4 heads)

__device__ __forceinline__ float lrelu(float x) { return x > 0.f ? x : 0.2f * x; }

// ---------------- CSR build ----------------
__global__ void k_hist(const int* __restrict__ ei) {
    int i = blockIdx.x * blockDim.x + threadIdx.x;
    if (i < EE) {
        atomicAdd(&g_deg[ei[EE + i]], 1);      // dst of edge i
    } else if (i < TOT) {
        atomicAdd(&g_deg[i - EE], 1);          // self loop
    }
}

__global__ void k_scan() {
    __shared__ int part[1024];
    int t = threadIdx.x;
    const int C = (NN + 1023) / 1024;  // 49
    int lo = t * C;
    int hi = lo + C;
    if (hi > NN) hi = NN;
    int s = 0;
    for (int i = lo; i < hi; i++) s += g_deg[i];
    part[t] = s;
    __syncthreads();
    for (int off = 1; off < 1024; off <<= 1) {
        int v = (t >= off) ? part[t - off] : 0;
        __syncthreads();
        part[t] += v;
        __syncthreads();
    }
    int run = (t > 0) ? part[t - 1] : 0;
    for (int i = lo; i < hi; i++) {
        g_rowptr[i] = run;
        g_cursor[i] = run;
        run += g_deg[i];
    }
    if (t == 1023) g_rowptr[NN] = part[1023];
}

__global__ void k_scatter(const int* __restrict__ ei) {
    int i = blockIdx.x * blockDim.x + threadIdx.x;
    if (i < EE) {
        int src = ei[i];
        int dst = ei[EE + i];
        int pos = atomicAdd(&g_cursor[dst], 1);
        g_csr[pos] = src;
        g_dstv[pos] = dst;
    } else if (i < TOT) {
        int v = i - EE;
        int pos = atomicAdd(&g_cursor[v], 1);
        g_csr[pos] = v;  // self loop
        g_dstv[pos] = v;
    }
}

// ---------------- GEMM1 + attn terms: h1 = x @ W1, as1/ad1 fused -----------
__global__ void __launch_bounds__(256) k_gemm1(const float* __restrict__ x,
                                               const float* __restrict__ W,
                                               const float* __restrict__ asrc,
                                               const float* __restrict__ adst) {
    extern __shared__ float sm[];
    float* Ws = sm;            // 16384 floats
    float* xs = sm + 16384;    // 64 * 132 floats (padded stride kills bank conflicts)
    int tid = threadIdx.x;
    int row0 = blockIdx.x * 64;

    const float4* W4 = (const float4*)W;
    float4* Ws4 = (float4*)Ws;
    for (int i = tid; i < 4096; i += 256) Ws4[i] = W4[i];
    for (int i = tid; i < 2048; i += 256) {
        int r = i >> 5, c4 = i & 31;
        float4 v;
        if (row0 + r < NN) v = ((const float4*)x)[(row0 + r) * 32 + c4];
        else v = make_float4(0.f, 0.f, 0.f, 0.f);
        *(float4*)&xs[r * 132 + c4 * 4] = v;
    }
    __syncthreads();

    int tx = tid & 31, ty = tid >> 5;
    float acc[8][4];
#pragma unroll
    for (int r = 0; r < 8; r++) { acc[r][0] = acc[r][1] = acc[r][2] = acc[r][3] = 0.f; }

    const float4* Wv = (const float4*)Ws;
#pragma unroll 8
    for (int k = 0; k < 128; k++) {
        float4 w = Wv[k * 32 + tx];
#pragma unroll
        for (int r = 0; r < 8; r++) {
            float xv = xs[(ty * 8 + r) * 132 + k];
            acc[r][0] = fmaf(xv, w.x, acc[r][0]);
            acc[r][1] = fmaf(xv, w.y, acc[r][1]);
            acc[r][2] = fmaf(xv, w.z, acc[r][2]);
            acc[r][3] = fmaf(xv, w.w, acc[r][3]);
        }
    }

    // epilogue: store h1 + fused attention terms (as1/ad1)
    float4 av = ((const float4*)asrc)[tx];
    float4 dv = ((const float4*)adst)[tx];
#pragma unroll
    for (int r = 0; r < 8; r++) {
        int row = row0 + ty * 8 + r;
        if (row < NN)
            ((float4*)g_h1)[row * 32 + tx] =
                make_float4(acc[r][0], acc[r][1], acc[r][2], acc[r][3]);
        float s = acc[r][0] * av.x + acc[r][1] * av.y + acc[r][2] * av.z + acc[r][3] * av.w;
        float d = acc[r][0] * dv.x + acc[r][1] * dv.y + acc[r][2] * dv.z + acc[r][3] * dv.w;
        s += __shfl_down_sync(0xffffffffu, s, 4);
        d += __shfl_down_sync(0xffffffffu, d, 4);
        s += __shfl_down_sync(0xffffffffu, s, 2);
        d += __shfl_down_sync(0xffffffffu, d, 2);
        s += __shfl_down_sync(0xffffffffu, s, 1);
        d += __shfl_down_sync(0xffffffffu, d, 1);
        if ((tx & 7) == 0 && row < NN) {
            g_as1[row * 4 + (tx >> 3)] = s;
            g_ad1[row * 4 + (tx >> 3)] = d;
        }
    }
}

// ---------------- per-edge softmax weights (edge-parallel, high MLP) --------
__global__ void k_edgep() {
    int j = blockIdx.x * blockDim.x + threadIdx.x;
    if (j >= TOT) return;
    int s = g_csr[j];
    int n = g_dstv[j];
    float4 av = *(const float4*)&g_as1[s * 4];
    float4 dv = *(const float4*)&g_ad1[n * 4];
    float4 p;
    p.x = __expf(lrelu(av.x + dv.x));
    p.y = __expf(lrelu(av.y + dv.y));
    p.z = __expf(lrelu(av.z + dv.z));
    p.w = __expf(lrelu(av.w + dv.w));
    g_p[j] = p;
}

// ---------------- layer-1 agg + relu + layer-2 linear ----------------------
// Warp = 4 edge-slots (e = lane>>3) x 8 channel-octets (c8 = lane&7).
// Each lane: 1 edge x 16 channels (4 float4 loads) per iteration ->
// 16 independent 128B lines in flight per warp, 4 edges retired/iter.
// Reduce: edge dim via shfl_xor 8,16; then W2 contraction over c8 via 1,2,4.
__global__ void k_agg1(const float* __restrict__ b1,
                       const float* __restrict__ W2,
                       const float* __restrict__ asrc2,
                       const float* __restrict__ adst2) {
    int g = blockIdx.x * blockDim.x + threadIdx.x;
    int n = g >> 5, lane = g & 31;
    if (n >= NN) return;
    int beg = g_rowptr[n], end = g_rowptr[n + 1];
    int e = lane >> 3;          // edge slot 0..3
    int c8 = lane & 7;          // channel octet 0..7 (channels c8*16..c8*16+15)
    int head = c8 >> 1;

    float4 acc0 = {0.f, 0.f, 0.f, 0.f}, acc1 = {0.f, 0.f, 0.f, 0.f};
    float4 acc2 = {0.f, 0.f, 0.f, 0.f}, acc3 = {0.f, 0.f, 0.f, 0.f};
    float den = 0.f;

    int iters = (end - beg + 3) >> 2;
    const float* pflat = (const float*)g_p;
    for (int t = 0; t < iters; t++) {
        int j = beg + t * 4 + e;
        bool valid = j < end;
        int s = valid ? g_csr[j] : g_csr[beg];           // safe row (self loop)
        float p = valid ? pflat[j * 4 + head] : 0.f;
        const float4* hr = (const float4*)&g_h1[s * 128 + c8 * 16];
        float4 v0 = hr[0], v1 = hr[1], v2 = hr[2], v3 = hr[3];
        acc0.x = fmaf(p, v0.x, acc0.x); acc0.y = fmaf(p, v0.y, acc0.y);
        acc0.z = fmaf(p, v0.z, acc0.z); acc0.w = fmaf(p, v0.w, acc0.w);
        acc1.x = fmaf(p, v1.x, acc1.x); acc1.y = fmaf(p, v1.y, acc1.y);
        acc1.z = fmaf(p, v1.z, acc1.z); acc1.w = fmaf(p, v1.w, acc1.w);
        acc2.x = fmaf(p, v2.x, acc2.x); acc2.y = fmaf(p, v2.y, acc2.y);
        acc2.z = fmaf(p, v2.z, acc2.z); acc2.w = fmaf(p, v2.w, acc2.w);
        acc3.x = fmaf(p, v3.x, acc3.x); acc3.y = fmaf(p, v3.y, acc3.y);
        acc3.z = fmaf(p, v3.z, acc3.z); acc3.w = fmaf(p, v3.w, acc3.w);
        den += p;
    }

    // reduce over the 4 edge slots (lanes differing in bits 3,4)
#pragma unroll
    for (int off = 8; off <= 16; off <<= 1) {
        acc0.x += __shfl_xor_sync(0xffffffffu, acc0.x, off);
        acc0.y += __shfl_xor_sync(0xffffffffu, acc0.y, off);
        acc0.z += __shfl_xor_sync(0xffffffffu, acc0.z, off);
        acc0.w += __shfl_xor_sync(0xffffffffu, acc0.w, off);
        acc1.x += __shfl_xor_sync(0xffffffffu, acc1.x, off);
        acc1.y += __shfl_xor_sync(0xffffffffu, acc1.y, off);
        acc1.z += __shfl_xor_sync(0xffffffffu, acc1.z, off);
        acc1.w += __shfl_xor_sync(0xffffffffu, acc1.w, off);
        acc2.x += __shfl_xor_sync(0xffffffffu, acc2.x, off);
        acc2.y += __shfl_xor_sync(0xffffffffu, acc2.y, off);
        acc2.z += __shfl_xor_sync(0xffffffffu, acc2.z, off);
        acc2.w += __shfl_xor_sync(0xffffffffu, acc2.w, off);
        acc3.x += __shfl_xor_sync(0xffffffffu, acc3.x, off);
        acc3.y += __shfl_xor_sync(0xffffffffu, acc3.y, off);
        acc3.z += __shfl_xor_sync(0xffffffffu, acc3.z, off);
        acc3.w += __shfl_xor_sync(0xffffffffu, acc3.w, off);
        den += __shfl_xor_sync(0xffffffffu, den, off);
    }

    // relu(acc/den + b1) for this lane's 16 channels, then W2 contraction
    float inv = 1.f / (den + 1e-16f);
    int c0i = c8 * 16;
    float c0 = 0.f, c1 = 0.f;
    float vals[16] = {acc0.x, acc0.y, acc0.z, acc0.w, acc1.x, acc1.y, acc1.z, acc1.w,
                      acc2.x, acc2.y, acc2.z, acc2.w, acc3.x, acc3.y, acc3.z, acc3.w};
#pragma unroll
    for (int q = 0; q < 16; q++) {
        float o = fmaxf(vals[q] * inv + __ldg(&b1[c0i + q]), 0.f);
        c0 = fmaf(o, __ldg(&W2[(c0i + q) * 2]), c0);
        c1 = fmaf(o, __ldg(&W2[(c0i + q) * 2 + 1]), c1);
    }
    // reduce over the 8 channel octets (lane bits 0,1,2)
#pragma unroll
    for (int off = 1; off <= 4; off <<= 1) {
        c0 += __shfl_xor_sync(0xffffffffu, c0, off);
        c1 += __shfl_xor_sync(0xffffffffu, c1, off);
    }
    if (lane == 0) {
        g_h2[2 * n]     = c0;
        g_h2[2 * n + 1] = c1;
        g_as2[n] = c0 * __ldg(&asrc2[0]) + c1 * __ldg(&asrc2[1]);
        g_ad2[n] = c0 * __ldg(&adst2[0]) + c1 * __ldg(&adst2[1]);
    }
}

// ---------------- layer-2 aggregation + log_softmax (warp per dst) ----------
__global__ void k_agg2(const float* __restrict__ b2, float* __restrict__ out) {
    int g = blockIdx.x * blockDim.x + threadIdx.x;
    int n = g >> 5, lane = g & 31;
    if (n >= NN) return;
    int beg = g_rowptr[n], end = g_rowptr[n + 1];
    float adv = g_ad2[n];

    float a0 = 0.f, a1 = 0.f, den = 0.f;
    for (int j = beg + lane; j < end; j += 32) {
        int s = g_csr[j];
        float p = __expf(lrelu(g_as2[s] + adv));
        float2 hv = *(const float2*)&g_h2[2 * s];
        a0 = fmaf(p, hv.x, a0);
        a1 = fmaf(p, hv.y, a1);
        den += p;
    }
#pragma unroll
    for (int off = 16; off; off >>= 1) {
        a0 += __shfl_xor_sync(0xffffffffu, a0, off);
        a1 += __shfl_xor_sync(0xffffffffu, a1, off);
        den += __shfl_xor_sync(0xffffffffu, den, off);
    }
    if (lane == 0) {
        float o0 = a0 / (den + 1e-16f) + b2[0];
        float o1 = a1 / (den + 1e-16f) + b2[1];
        float mm = fmaxf(o0, o1);
        float lse = mm + logf(expf(o0 - mm) + expf(o1 - mm));
        out[2 * n]     = o0 - lse;
        out[2 * n + 1] = o1 - lse;
    }
}

// ---------------- launch ----------------
extern "C" void kernel_launch(void* const* d_in, const int* in_sizes, int n_in,
                              void* d_out, int out_size) {
    (void)in_sizes; (void)n_in; (void)out_size;
    const float* x     = (const float*)d_in[0];
    const int*   ei    = (const int*)d_in[1];   // [2, E]: first E = src, next E = dst
    const float* W1    = (const float*)d_in[2];
    const float* asrc1 = (const float*)d_in[3];
    const float* adst1 = (const float*)d_in[4];
    const float* b1    = (const float*)d_in[5];
    const float* W2    = (const float*)d_in[6];
    const float* asrc2 = (const float*)d_in[7];
    const float* adst2 = (const float*)d_in[8];
    const float* b2    = (const float*)d_in[9];
    float* out = (float*)d_out;

    static cudaStream_t s1 = nullptr;
    static cudaEvent_t evFork = nullptr, evJoin = nullptr;
    if (s1 == nullptr) {
        cudaStreamCreateWithFlags(&s1, cudaStreamNonBlocking);
        cudaEventCreateWithFlags(&evFork, cudaEventDisableTiming);
        cudaEventCreateWithFlags(&evJoin, cudaEventDisableTiming);
    }

    cudaFuncSetAttribute(k_gemm1, cudaFuncAttributeMaxDynamicSharedMemorySize, 99328);

    void* degPtr = nullptr;
    cudaGetSymbolAddress(&degPtr, g_deg);

    // fork: CSR build on s1, concurrent with gemm1 on the main stream
    cudaEventRecord(evFork, 0);
    cudaStreamWaitEvent(s1, evFork, 0);
    cudaMemsetAsync(degPtr, 0, NN * sizeof(int), s1);
    k_hist<<<(TOT + 255) / 256, 256, 0, s1>>>(ei);
    k_scan<<<1, 1024, 0, s1>>>();
    k_scatter<<<(TOT + 255) / 256, 256, 0, s1>>>(ei);
    cudaEventRecord(evJoin, s1);

    // layer 1 linear (FFMA, proven) + fused attn terms — overlaps CSR build
    k_gemm1<<<(NN + 63) / 64, 256, 99328>>>(x, W1, asrc1, adst1);

    // join: everything after needs both gemm1 outputs and the CSR
    cudaStreamWaitEvent(0, evJoin, 0);

    // per-edge softmax weights (edge-parallel)
    k_edgep<<<(TOT + 255) / 256, 256>>>();
    // layer-1 agg + relu + layer-2 linear fused (4-edge x 8-octet warp layout)
    k_agg1<<<(NN * 32 + 255) / 256, 256>>>(b1, W2, asrc2, adst2);
    // layer-2 aggregation + log_softmax
    k_agg2<<<(NN * 32 + 255) / 256, 256>>>(b2, out);
}